// round 1
// baseline (speedup 1.0000x reference)
#include <cuda_runtime.h>
#include <math.h>

#define BB   8
#define NN   4096
#define DD   64
#define KNN  20
#define OO   64

// ---------------- scratch (__device__ globals: allocation-free) ----------------
__device__ float g_sq[BB*NN];
__device__ float g_y [BB*NN*OO];
__device__ float g_z [BB*NN*OO];
__device__ int   g_idx[BB*NN*KNN];
__device__ float g_h [BB*NN*OO];
__device__ float g_psum[128*OO];
__device__ float g_psq [128*OO];
__device__ float g_a [OO];
__device__ float g_bb2[OO];

// ---------------- kernel 1: per-point sumsq, y = x·w1^T, z = x·(w2-w1)^T -------
__global__ __launch_bounds__(128) void prep_kernel(const float* __restrict__ x,
                                                   const float* __restrict__ w)
{
    __shared__ float ws[64*128];
    int tid = threadIdx.x;
    #pragma unroll
    for (int i = 0; i < 64; i++) ws[i*128 + tid] = w[i*128 + tid];
    __syncthreads();

    int b = blockIdx.y;
    int n = blockIdx.x * 128 + tid;
    const float* xb = x + b * (DD*NN);

    float p[DD];
    float sq = 0.f;
    #pragma unroll
    for (int d = 0; d < DD; d++) { p[d] = xb[d*NN + n]; sq = fmaf(p[d], p[d], sq); }
    g_sq[b*NN + n] = sq;

    float* yp = g_y + (b*NN + n)*OO;
    float* zp = g_z + (b*NN + n)*OO;
    #pragma unroll 4
    for (int o = 0; o < OO; o++) {
        float ya = 0.f, za = 0.f;
        #pragma unroll
        for (int d = 0; d < DD; d++) {
            float w1 = ws[o*128 + d];
            float w2 = ws[o*128 + 64 + d];
            ya = fmaf(p[d], w1, ya);
            za = fmaf(p[d], w2 - w1, za);
        }
        yp[o] = ya; zp[o] = za;
    }
}

// ---------------- kernel 2: fused Gram + running top-20 ------------------------
__device__ __forceinline__ void topk_insert(float (&best)[KNN], int (&bidx)[KNN],
                                            float c, int m)
{
    if (c < best[KNN-1]) {
        best[KNN-1] = c; bidx[KNN-1] = m;
        #pragma unroll
        for (int t = KNN-1; t > 0; --t) {
            if (best[t-1] > best[t]) {
                float tf = best[t-1]; best[t-1] = best[t]; best[t] = tf;
                int   ti = bidx[t-1]; bidx[t-1] = bidx[t]; bidx[t] = ti;
            }
        }
    }
}

__global__ __launch_bounds__(128) void knn_kernel(const float* __restrict__ x)
{
    __shared__ float s[64][128];
    __shared__ float ssq[128];

    int tid = threadIdx.x;
    int b = blockIdx.y;
    int r = blockIdx.x * 128 + tid;
    const float* xb = x + b * (DD*NN);

    float p[DD];
    #pragma unroll
    for (int d = 0; d < DD; d++) p[d] = xb[d*NN + r];

    float best[KNN];
    int   bidx[KNN];
    #pragma unroll
    for (int j = 0; j < KNN; j++) { best[j] = 3.4e38f; bidx[j] = 0; }

    for (int m0 = 0; m0 < NN; m0 += 128) {
        __syncthreads();
        #pragma unroll
        for (int d = 0; d < 64; d++) s[d][tid] = xb[d*NN + m0 + tid];
        ssq[tid] = g_sq[b*NN + m0 + tid];
        __syncthreads();

        #pragma unroll 1
        for (int m = 0; m < 128; m += 4) {
            float a0 = 0.f, a1 = 0.f, a2 = 0.f, a3 = 0.f;
            #pragma unroll
            for (int d = 0; d < 64; d++) {
                float4 v = *reinterpret_cast<const float4*>(&s[d][m]);
                float pd = p[d];
                a0 = fmaf(pd, v.x, a0);
                a1 = fmaf(pd, v.y, a1);
                a2 = fmaf(pd, v.z, a2);
                a3 = fmaf(pd, v.w, a3);
            }
            // ranking criterion: d2 - sq[r] = sq[m] - 2*dot (monotone in d2)
            float c0 = ssq[m+0] - 2.f*a0;
            float c1 = ssq[m+1] - 2.f*a1;
            float c2 = ssq[m+2] - 2.f*a2;
            float c3 = ssq[m+3] - 2.f*a3;
            topk_insert(best, bidx, c0, m0+m+0);
            topk_insert(best, bidx, c1, m0+m+1);
            topk_insert(best, bidx, c2, m0+m+2);
            topk_insert(best, bidx, c3, m0+m+3);
        }
    }

    int* op = g_idx + (b*NN + r)*KNN;
    #pragma unroll
    for (int j = 0; j < KNN; j++) op[j] = bidx[j];
}

// ---------------- kernel 3: gather-max + h + BN partial sums -------------------
__global__ __launch_bounds__(256) void hmax_kernel()
{
    int tid = threadIdx.x;
    int warp = tid >> 5, lane = tid & 31;
    int b = blockIdx.y;
    int nbase = blockIdx.x * 256 + warp * 32;
    const float* yb = g_y + b*NN*OO;

    float s0 = 0.f, s1 = 0.f, q0 = 0.f, q1 = 0.f;
    for (int i = 0; i < 32; i++) {
        int n = nbase + i;
        const int* ip = g_idx + (b*NN + n)*KNN;
        float m0v = -3.4e38f, m1v = -3.4e38f;
        #pragma unroll
        for (int k = 0; k < KNN; k++) {
            int m = ip[k];
            const float* yr = yb + m*OO;
            m0v = fmaxf(m0v, yr[lane]);
            m1v = fmaxf(m1v, yr[lane + 32]);
        }
        const float* zr = g_z + (b*NN + n)*OO;
        float h0 = zr[lane]      + m0v;
        float h1 = zr[lane + 32] + m1v;
        g_h[(b*NN + n)*OO + lane]      = h0;
        g_h[(b*NN + n)*OO + lane + 32] = h1;
        s0 += h0; s1 += h1;
        q0 = fmaf(h0, h0, q0); q1 = fmaf(h1, h1, q1);
    }

    __shared__ float ps[8][64], pq[8][64];
    ps[warp][lane]      = s0; ps[warp][lane + 32] = s1;
    pq[warp][lane]      = q0; pq[warp][lane + 32] = q1;
    __syncthreads();
    if (tid < 64) {
        float S = 0.f, Q = 0.f;
        #pragma unroll
        for (int wr = 0; wr < 8; wr++) { S += ps[wr][tid]; Q += pq[wr][tid]; }
        int blk = b*16 + blockIdx.x;
        g_psum[blk*64 + tid] = S;
        g_psq [blk*64 + tid] = Q;
    }
}

// ---------------- kernel 4: deterministic fp64 stats reduce --------------------
__global__ void stats_kernel(const float* __restrict__ gamma,
                             const float* __restrict__ beta)
{
    int ch = threadIdx.x;            // 64 threads
    double S = 0.0, Q = 0.0;
    for (int i = 0; i < 128; i++) {
        S += (double)g_psum[i*64 + ch];
        Q += (double)g_psq [i*64 + ch];
    }
    double cnt  = (double)(BB * NN);
    double mean = S / cnt;
    double var  = Q / cnt - mean * mean;
    float inv = (float)(1.0 / sqrt(var + 1e-5));
    float a = gamma[ch] * inv;
    g_a  [ch] = a;
    g_bb2[ch] = beta[ch] - (float)mean * a;
}

// ---------------- kernel 5: BN affine + exact GELU + transpose -----------------
__global__ __launch_bounds__(256) void final_kernel(float* __restrict__ out)
{
    __shared__ float t[64][65];
    int tid = threadIdx.x;
    int b = blockIdx.y;
    int n0 = blockIdx.x * 64;
    const float* hb = g_h + b*NN*OO;

    #pragma unroll
    for (int it = 0; it < 16; it++) {
        int idx = it*256 + tid;
        int nl = idx >> 6, o = idx & 63;
        t[nl][o] = hb[(n0 + nl)*OO + o];
    }
    __syncthreads();

    float* ob = out + b*OO*NN;
    #pragma unroll
    for (int it = 0; it < 16; it++) {
        int idx = it*256 + tid;
        int o = idx >> 6, nl = idx & 63;
        float v = t[nl][o] * g_a[o] + g_bb2[o];
        ob[o*NN + n0 + nl] = 0.5f * v * (1.f + erff(v * 0.70710678118654752f));
    }
}

// ---------------- launch --------------------------------------------------------
extern "C" void kernel_launch(void* const* d_in, const int* in_sizes, int n_in,
                              void* d_out, int out_size)
{
    const float* x     = (const float*)d_in[0];
    const float* w     = (const float*)d_in[1];
    const float* gamma = (const float*)d_in[2];
    const float* beta  = (const float*)d_in[3];
    float* out = (float*)d_out;

    prep_kernel <<<dim3(NN/128, BB), 128>>>(x, w);
    knn_kernel  <<<dim3(NN/128, BB), 128>>>(x);
    hmax_kernel <<<dim3(NN/256, BB), 256>>>();
    stats_kernel<<<1, 64>>>(gamma, beta);
    final_kernel<<<dim3(NN/64, BB), 256>>>(out);
}